// round 1
// baseline (speedup 1.0000x reference)
#include <cuda_runtime.h>
#include <math.h>

#define DIMC   64
#define NV     25
#define TLEN   64
#define NSTEP  3
#define NE     (DIMC * NV)      // 1600 elements per sample state
#define LEAK   0.01f
#define NTHR   256

// ---- shared memory layout (floats) ----
// Wt1[64*64] Wt2[64*64] Wtp[64*64]  (transposed: Wt[c*64+o] = W[o*64+c])
// At[25*25 -> pad 640]              (transposed: At[u*25+v] = A[v*25+u])
// b1[64] b2[64] bp[64]
// pe[(TLEN+NSTEP)*64 = 67*64 = 4288]
// buffers: y, k1, k2, k3, tA, tB   each 1600
#define OFF_WT1  0
#define OFF_WT2  4096
#define OFF_WTP  8192
#define OFF_AT   12288
#define OFF_B1   12928
#define OFF_B2   12992
#define OFF_BP   13056
#define OFF_PE   13120
#define OFF_BUF  17408           // 13120 + 4288
#define SM_FLOATS (OFF_BUF + 6 * NE)      // 27008 floats
#define SM_BYTES  (SM_FLOATS * 4)          // 108032 bytes

__device__ __forceinline__ float lrelu(float x) {
    return x >= 0.0f ? x : LEAK * x;
}

// out[o,v] = act( sum_c Wt[c*64+o] * in[c*25+v] + b[o] )
// thread tile: 4 o's x up-to-2 v's
template<bool ACT>
__device__ __forceinline__ void wmat(const float* Wt, const float* bias,
                                     const float* in, float* out, int tid)
{
    const int vq = tid & 15;
    const int oq = tid >> 4;          // 0..15
    const int o0 = oq * 4;
    const int v1 = vq + 16;
    const bool hv1 = (v1 < NV);

    float a00 = 0.f, a01 = 0.f, a10 = 0.f, a11 = 0.f;
    float a20 = 0.f, a21 = 0.f, a30 = 0.f, a31 = 0.f;

#pragma unroll 8
    for (int c = 0; c < DIMC; c++) {
        const float x0 = in[c * NV + vq];
        const float x1 = hv1 ? in[c * NV + v1] : 0.f;
        const float* wr = Wt + c * 64 + o0;
        const float w0 = wr[0], w1 = wr[1], w2 = wr[2], w3 = wr[3];
        a00 += w0 * x0;  a01 += w0 * x1;
        a10 += w1 * x0;  a11 += w1 * x1;
        a20 += w2 * x0;  a21 += w2 * x1;
        a30 += w3 * x0;  a31 += w3 * x1;
    }

    const float bb0 = bias[o0 + 0], bb1 = bias[o0 + 1];
    const float bb2 = bias[o0 + 2], bb3 = bias[o0 + 3];

    float r00 = a00 + bb0, r10 = a10 + bb1, r20 = a20 + bb2, r30 = a30 + bb3;
    if (ACT) { r00 = lrelu(r00); r10 = lrelu(r10); r20 = lrelu(r20); r30 = lrelu(r30); }
    out[(o0 + 0) * NV + vq] = r00;
    out[(o0 + 1) * NV + vq] = r10;
    out[(o0 + 2) * NV + vq] = r20;
    out[(o0 + 3) * NV + vq] = r30;
    if (hv1) {
        float r01 = a01 + bb0, r11 = a11 + bb1, r21 = a21 + bb2, r31 = a31 + bb3;
        if (ACT) { r01 = lrelu(r01); r11 = lrelu(r11); r21 = lrelu(r21); r31 = lrelu(r31); }
        out[(o0 + 0) * NV + v1] = r01;
        out[(o0 + 1) * NV + v1] = r11;
        out[(o0 + 2) * NV + v1] = r21;
        out[(o0 + 3) * NV + v1] = r31;
    }
}

// out[c,v] = sum_u in[c*25+u] * At[u*25+v]
// thread tile: 4 c's x up-to-2 v's
__device__ __forceinline__ void amat(const float* At, const float* in, float* out, int tid)
{
    const int vq = tid & 15;
    const int cq = tid >> 4;
    const int c0 = cq * 4;
    const int v1 = vq + 16;
    const bool hv1 = (v1 < NV);

    float a00 = 0.f, a01 = 0.f, a10 = 0.f, a11 = 0.f;
    float a20 = 0.f, a21 = 0.f, a30 = 0.f, a31 = 0.f;

#pragma unroll 5
    for (int u = 0; u < NV; u++) {
        const float s0 = At[u * NV + vq];
        const float s1 = hv1 ? At[u * NV + v1] : 0.f;
        const float x0 = in[(c0 + 0) * NV + u];
        const float x1 = in[(c0 + 1) * NV + u];
        const float x2 = in[(c0 + 2) * NV + u];
        const float x3 = in[(c0 + 3) * NV + u];
        a00 += x0 * s0;  a01 += x0 * s1;
        a10 += x1 * s0;  a11 += x1 * s1;
        a20 += x2 * s0;  a21 += x2 * s1;
        a30 += x3 * s0;  a31 += x3 * s1;
    }
    out[(c0 + 0) * NV + vq] = a00;
    out[(c0 + 1) * NV + vq] = a10;
    out[(c0 + 2) * NV + vq] = a20;
    out[(c0 + 3) * NV + vq] = a30;
    if (hv1) {
        out[(c0 + 0) * NV + v1] = a01;
        out[(c0 + 1) * NV + v1] = a11;
        out[(c0 + 2) * NV + v1] = a21;
        out[(c0 + 3) * NV + v1] = a31;
    }
}

// Full ode_func given arg already in tB (pe included). Result -> dst.
__device__ __forceinline__ void ode_eval(const float* At,
                                         const float* Wt1, const float* b1,
                                         const float* Wt2, const float* b2,
                                         const float* Wtp, const float* bp,
                                         float* tA, float* tB, float* dst, int tid)
{
    __syncthreads();                      // tB (arg) ready
    amat(At, tB, tA, tid);  __syncthreads();
    wmat<true>(Wt1, b1, tA, tB, tid);  __syncthreads();
    amat(At, tB, tA, tid);  __syncthreads();
    wmat<true>(Wt2, b2, tA, tB, tid);  __syncthreads();
    wmat<false>(Wtp, bp, tB, dst, tid);  __syncthreads();
}

__global__ void __launch_bounds__(NTHR)
sode_kernel(const float* __restrict__ gfp,   // first_point (B, 64, 25)
            const float* __restrict__ gts,   // time_steps (4)
            const float* __restrict__ gA,    // (25,25)
            const float* __restrict__ gW1, const float* __restrict__ gb1,
            const float* __restrict__ gW2, const float* __restrict__ gb2,
            const float* __restrict__ gWp, const float* __restrict__ gbp,
            const float* __restrict__ gpe,   // (67, 64)
            float* __restrict__ out,         // (4, B, 64, 25)
            int nb)
{
    extern __shared__ float sm[];
    float* Wt1 = sm + OFF_WT1;
    float* Wt2 = sm + OFF_WT2;
    float* Wtp = sm + OFF_WTP;
    float* At  = sm + OFF_AT;
    float* b1  = sm + OFF_B1;
    float* b2  = sm + OFF_B2;
    float* bp  = sm + OFF_BP;
    float* pe  = sm + OFF_PE;
    float* y   = sm + OFF_BUF + 0 * NE;
    float* k1  = sm + OFF_BUF + 1 * NE;
    float* k2  = sm + OFF_BUF + 2 * NE;
    float* k3  = sm + OFF_BUF + 3 * NE;
    float* tA  = sm + OFF_BUF + 4 * NE;
    float* tB  = sm + OFF_BUF + 5 * NE;

    const int tid = threadIdx.x;
    const int n = blockIdx.x;
    const int tt = n & (TLEN - 1);

    // --- cooperative loads of weights (transposed) ---
    for (int i = tid; i < DIMC * DIMC; i += NTHR) {
        const int o = i >> 6, c = i & 63;
        Wt1[c * 64 + o] = gW1[i];
        Wt2[c * 64 + o] = gW2[i];
        Wtp[c * 64 + o] = gWp[i];
    }
    for (int i = tid; i < NV * NV; i += NTHR) {
        const int v = i / NV, u = i % NV;
        At[u * NV + v] = gA[i];
    }
    if (tid < DIMC) { b1[tid] = gb1[tid]; b2[tid] = gb2[tid]; bp[tid] = gbp[tid]; }
    for (int i = tid; i < (TLEN + NSTEP) * DIMC; i += NTHR) pe[i] = gpe[i];

    // --- load state, emit out[0] ---
    const float* fp = gfp + (size_t)n * NE;
    float* out0 = out + (size_t)n * NE;
    for (int e = tid; e < NE; e += NTHR) {
        const float v = fp[e];
        y[e] = v;
        out0[e] = v;
    }
    __syncthreads();

    for (int s = 0; s < NSTEP; s++) {
        const float t0 = gts[s];
        const float dt = gts[s + 1] - gts[s];

        // ---- k1: arg = y ----
        {
            const int ti = (int)floorf(t0);
            const float* per = pe + (ti + tt) * DIMC;
            for (int e = tid; e < NE; e += NTHR)
                tB[e] = y[e] + per[e / NV];
        }
        ode_eval(At, Wt1, b1, Wt2, b2, Wtp, bp, tA, tB, k1, tid);

        // ---- k2: arg = y + dt/3 * k1 ----
        {
            const int ti = (int)floorf(t0 + dt * (1.f / 3.f));
            const float* per = pe + (ti + tt) * DIMC;
            const float f = dt * (1.f / 3.f);
            for (int e = tid; e < NE; e += NTHR)
                tB[e] = y[e] + f * k1[e] + per[e / NV];
        }
        ode_eval(At, Wt1, b1, Wt2, b2, Wtp, bp, tA, tB, k2, tid);

        // ---- k3: arg = y + dt*(k2 - k1/3) ----
        {
            const int ti = (int)floorf(t0 + dt * (2.f / 3.f));
            const float* per = pe + (ti + tt) * DIMC;
            for (int e = tid; e < NE; e += NTHR)
                tB[e] = y[e] + dt * (k2[e] - k1[e] * (1.f / 3.f)) + per[e / NV];
        }
        ode_eval(At, Wt1, b1, Wt2, b2, Wtp, bp, tA, tB, k3, tid);

        // ---- k4: arg = y + dt*(k1 - k2 + k3); fold k2 <- k1 + 3*(k2+k3) ----
        {
            const int ti = (int)floorf(t0 + dt);
            const float* per = pe + (ti + tt) * DIMC;
            for (int e = tid; e < NE; e += NTHR) {
                const float v1 = k1[e], v2 = k2[e], v3 = k3[e];
                tB[e] = y[e] + dt * (v1 - v2 + v3) + per[e / NV];
                k2[e] = v1 + 3.f * (v2 + v3);
            }
        }
        ode_eval(At, Wt1, b1, Wt2, b2, Wtp, bp, tA, tB, k1, tid);  // k4 -> k1

        // ---- y += dt*(acc + k4)/8 ; emit out[s+1] ----
        {
            float* outs = out + (size_t)(s + 1) * nb * NE + (size_t)n * NE;
            const float f = dt * 0.125f;
            for (int e = tid; e < NE; e += NTHR) {
                const float ny = y[e] + f * (k2[e] + k1[e]);
                y[e] = ny;
                outs[e] = ny;
            }
        }
        __syncthreads();
    }
}

extern "C" void kernel_launch(void* const* d_in, const int* in_sizes, int n_in,
                              void* d_out, int out_size)
{
    const float* fp  = (const float*)d_in[0];
    const float* ts  = (const float*)d_in[1];
    const float* A   = (const float*)d_in[2];
    const float* W1  = (const float*)d_in[3];
    const float* b1  = (const float*)d_in[4];
    const float* W2  = (const float*)d_in[5];
    const float* b2  = (const float*)d_in[6];
    const float* Wp  = (const float*)d_in[7];
    const float* bp  = (const float*)d_in[8];
    const float* pe  = (const float*)d_in[9];
    float* out = (float*)d_out;

    const int nb = in_sizes[0] / NE;   // number of samples (16384)

    cudaFuncSetAttribute(sode_kernel,
                         cudaFuncAttributeMaxDynamicSharedMemorySize, SM_BYTES);

    sode_kernel<<<nb, NTHR, SM_BYTES>>>(fp, ts, A, W1, b1, W2, b2, Wp, bp, pe,
                                        out, nb);
}